// round 9
// baseline (speedup 1.0000x reference)
#include <cuda_runtime.h>

#define TPB     384
#define NODES   96
#define KU      8                   // u per chunk
#define NCHUNK  16
#define XS      76                  // per node per chunk: x0(8)+x1(24)+x2(40)+pad(4)
#define XBUF    (NODES * XS)        // 7296 floats per buffer
#define OFF_W1  (2 * XBUF)          // 14592 (w1_1: 2048 floats)
#define OFF_W2  (OFF_W1 + 2048)    // 16640 (w1_2: 2048)
#define OFF_W2S (OFF_W2 + 2048)    // 18688 (w2_*: 48)
#define SM_FLOATS (OFF_W2S + 48)   // 18736 floats = 74944 B -> 2 blocks/SM

typedef unsigned long long u64;

__device__ __forceinline__ u64 ffma2(u64 a, u64 b, u64 c) {
    u64 d;
    asm("fma.rn.f32x2 %0, %1, %2, %3;" : "=l"(d) : "l"(a), "l"(b), "l"(c));
    return d;
}
__device__ __forceinline__ u64 dup2(float v) {
    u64 d; unsigned u = __float_as_uint(v);
    asm("mov.b64 %0, {%1, %1};" : "=l"(d) : "r"(u));
    return d;
}
__device__ __forceinline__ void unpack2(u64 a, float& lo, float& hi) {
    lo = __uint_as_float((unsigned)a);
    hi = __uint_as_float((unsigned)(a >> 32));
}
__device__ __forceinline__ float silu(float v) {
    return v / (1.f + __expf(-v));
}

__global__ void __launch_bounds__(TPB, 2)
readout_kernel(const float* __restrict__ x,
               const float* __restrict__ w1_0, const float* __restrict__ w1_1,
               const float* __restrict__ w1_2, const float* __restrict__ w2_0,
               const float* __restrict__ w2_1, const float* __restrict__ w2_2,
               float* __restrict__ out, int n)
{
    extern __shared__ float sm[];
    const int tid = threadIdx.x;
    const int node0 = blockIdx.x * NODES;
    const unsigned smbase = (unsigned)__cvta_generic_to_shared(sm);

    // ---- cp.async staging: 96 nodes x 18 float4 per chunk = 1728 over 384 thr ----
    unsigned pk_dst[5];
    int pk_goff[5];
#pragma unroll
    for (int k = 0; k < 5; ++k) {
        int f = tid + k * TPB;
        if (f >= 18 * NODES) { pk_dst[k] = 0xFFFFFFFFu; pk_goff[k] = 0; continue; }
        int nd = f / 18, r = f - nd * 18;
        int sb, sc, dl;
        if (r < 2)      { sb = 4 * r;             sc = 8;  dl = 4 * r; }
        else if (r < 8) { sb = 128 + 4 * (r - 2); sc = 24; dl = 8 + 4 * (r - 2); }
        else            { sb = 512 + 4 * (r - 8); sc = 40; dl = 32 + 4 * (r - 8); }
        int gn = node0 + nd;
        if (gn >= n) gn = n - 1;                 // clamp; output stores are guarded
        pk_goff[k] = gn * 1152 + sb;
        pk_dst[k]  = (unsigned)((nd * XS + dl) * 4) | ((unsigned)sc << 20);
    }
    auto stage = [&](int c, int buf) {
#pragma unroll
        for (int k = 0; k < 5; ++k) {
            unsigned d = pk_dst[k];
            if (d == 0xFFFFFFFFu) break;
            const float* src = x + pk_goff[k] + (int)((d >> 20) & 63u) * c;
            unsigned dst = smbase + (unsigned)(buf * (XBUF * 4)) + (d & 0xFFFFFu);
            asm volatile("cp.async.cg.shared.global [%0], [%1], 16;"
                         :: "r"(dst), "l"(src));
        }
    };

    stage(0, 0);
    asm volatile("cp.async.commit_group;" ::: "memory");

    // small weights to smem (w1_0 stays in global, served by L1)
    for (int i = tid; i < 2048; i += TPB) sm[OFF_W1 + i] = w1_1[i];
    for (int i = tid; i < 2048; i += TPB) sm[OFF_W2 + i] = w1_2[i];
    if (tid < 16) {
        sm[OFF_W2S + tid]      = w2_0[tid];
        sm[OFF_W2S + 16 + tid] = w2_1[tid];
        sm[OFF_W2S + 32 + tid] = w2_2[tid];
    }

    // 12 warps = 3 groups x 4 roles; role interleaved across SMSPs
    const int w    = tid >> 5;
    const int lane = tid & 31;
    const int grp  = w >> 2;
    const int role = (w + grp) & 3;     // 0:y0(48v) 1:y1(16v x3i) 2,3:y2(8v x5i)
    const int node = grp * 32 + lane;

    u64 A[24];
#pragma unroll
    for (int i = 0; i < 24; ++i) A[i] = 0ull;

#pragma unroll 1
    for (int c = 0; c < NCHUNK; ++c) {
        if (c + 1 < NCHUNK) {
            stage(c + 1, (c + 1) & 1);
            asm volatile("cp.async.commit_group;" ::: "memory");
            asm volatile("cp.async.wait_group 1;" ::: "memory");
        } else {
            asm volatile("cp.async.wait_group 0;" ::: "memory");
        }
        __syncthreads();

        const float* xr = sm + (c & 1) * XBUF + node * XS;
        const int u0 = KU * c;

        if (role == 0) {
            // y0: all 48 outputs as 24 f32x2 pairs; weights via L1-cached LDG
            float4 xa = *(const float4*)xr;
            float4 xb = *(const float4*)(xr + 4);
            float xe[8] = { xa.x, xa.y, xa.z, xa.w, xb.x, xb.y, xb.z, xb.w };
#pragma unroll
            for (int u = 0; u < 8; ++u) {
                u64 xs2 = dup2(xe[u]);
                const ulonglong2* wr =
                    reinterpret_cast<const ulonglong2*>(w1_0 + (u0 + u) * 48);
#pragma unroll
                for (int j = 0; j < 12; ++j) {
                    ulonglong2 wv = __ldg(wr + j);
                    A[2 * j]     = ffma2(xs2, wv.x, A[2 * j]);
                    A[2 * j + 1] = ffma2(xs2, wv.y, A[2 * j + 1]);
                }
            }
        } else if (role == 1) {
            // y1: all 16 v x i=0..2 -> A[i*8+p]
#pragma unroll
            for (int h = 0; h < 2; ++h) {
                const float4* xp = (const float4*)(xr + 8 + 12 * h);
                float4 q0 = xp[0], q1 = xp[1], q2 = xp[2];
                float xe[12] = { q0.x,q0.y,q0.z,q0.w, q1.x,q1.y,q1.z,q1.w,
                                 q2.x,q2.y,q2.z,q2.w };
#pragma unroll
                for (int ul = 0; ul < 4; ++ul) {
                    const ulonglong2* wr =
                        (const ulonglong2*)(sm + OFF_W1 + (u0 + 4 * h + ul) * 16);
                    ulonglong2 wa = wr[0], wb = wr[1], wc = wr[2], wd = wr[3];
#pragma unroll
                    for (int i = 0; i < 3; ++i) {
                        u64 xs2 = dup2(xe[3 * ul + i]);
                        A[i * 8 + 0] = ffma2(xs2, wa.x, A[i * 8 + 0]);
                        A[i * 8 + 1] = ffma2(xs2, wa.y, A[i * 8 + 1]);
                        A[i * 8 + 2] = ffma2(xs2, wb.x, A[i * 8 + 2]);
                        A[i * 8 + 3] = ffma2(xs2, wb.y, A[i * 8 + 3]);
                        A[i * 8 + 4] = ffma2(xs2, wc.x, A[i * 8 + 4]);
                        A[i * 8 + 5] = ffma2(xs2, wc.y, A[i * 8 + 5]);
                        A[i * 8 + 6] = ffma2(xs2, wd.x, A[i * 8 + 6]);
                        A[i * 8 + 7] = ffma2(xs2, wd.y, A[i * 8 + 7]);
                    }
                }
            }
        } else {
            // y2: 8 v ((role-2)*8..+7) x i=0..4 -> A[i*4+p]
            const int v0 = (role - 2) * 8;
#pragma unroll
            for (int h = 0; h < 2; ++h) {
                const float4* xp = (const float4*)(xr + 32 + 20 * h);
                float4 q0 = xp[0], q1 = xp[1], q2 = xp[2], q3 = xp[3], q4 = xp[4];
                float xe[20] = { q0.x,q0.y,q0.z,q0.w, q1.x,q1.y,q1.z,q1.w,
                                 q2.x,q2.y,q2.z,q2.w, q3.x,q3.y,q3.z,q3.w,
                                 q4.x,q4.y,q4.z,q4.w };
#pragma unroll
                for (int ul = 0; ul < 4; ++ul) {
                    const ulonglong2* wr =
                        (const ulonglong2*)(sm + OFF_W2 + (u0 + 4 * h + ul) * 16 + v0);
                    ulonglong2 wa = wr[0], wb = wr[1];
#pragma unroll
                    for (int i = 0; i < 5; ++i) {
                        u64 xs2 = dup2(xe[5 * ul + i]);
                        A[i * 4 + 0] = ffma2(xs2, wa.x, A[i * 4 + 0]);
                        A[i * 4 + 1] = ffma2(xs2, wa.y, A[i * 4 + 1]);
                        A[i * 4 + 2] = ffma2(xs2, wb.x, A[i * 4 + 2]);
                        A[i * 4 + 3] = ffma2(xs2, wb.y, A[i * 4 + 3]);
                    }
                }
            }
        }
        __syncthreads();   // protect next stage() from overwriting live buffer
    }

    const float inv_in = 0.08838834764831845f;   // 1/sqrt(128)

    // ---- phase A: dump y0 (48) + y1 (48) per node into sm[node*96 ..] ----
    if (role == 0) {
        float* yb = sm + node * 96;
#pragma unroll
        for (int j = 0; j < 24; ++j) {
            float lo, hi; unpack2(A[j], lo, hi);
            yb[2 * j] = lo; yb[2 * j + 1] = hi;
        }
    } else if (role == 1) {
        float* yb = sm + node * 96;
#pragma unroll
        for (int i = 0; i < 3; ++i)
#pragma unroll
            for (int p = 0; p < 8; ++p) {
                float lo, hi; unpack2(A[i * 8 + p], lo, hi);
                yb[48 + (2 * p) * 3 + i]     = lo;
                yb[48 + (2 * p + 1) * 3 + i] = hi;
            }
    }
    __syncthreads();

    // ---- phase A compute: out[0..3] + stash g2 = silu(y0[32:48]) ----
    {
        const int nd = tid >> 2, k = tid & 3;
        const float* yn = sm + nd * 96;
        float g2v[4];
#pragma unroll
        for (int j = 0; j < 4; ++j)
            g2v[j] = silu(yn[32 + 4 * k + j] * inv_in);
        float o = 0.f;
        if (k == 0) {
#pragma unroll
            for (int h = 0; h < 16; ++h)
                o += silu(yn[h] * inv_in) * sm[OFF_W2S + h];
        } else {
            const int i = k - 1;
#pragma unroll
            for (int v = 0; v < 16; ++v)
                o += silu(yn[16 + v] * inv_in) * (yn[48 + 3 * v + i] * inv_in)
                     * sm[OFF_W2S + 16 + v];
        }
        __syncthreads();   // ensure all reads of yn done before phase B overwrites
        // stash g2 after the sync barrier region decision: g2 lives at 9216+
        sm[9216 + nd * 16 + 4 * k + 0] = g2v[0];
        sm[9216 + nd * 16 + 4 * k + 1] = g2v[1];
        sm[9216 + nd * 16 + 4 * k + 2] = g2v[2];
        sm[9216 + nd * 16 + 4 * k + 3] = g2v[3];
        const int gn = node0 + nd;
        if (gn < n) out[gn * 9 + k] = o * 0.25f;
    }
    __syncthreads();

    // ---- phase B: dump y2 (80 per node) into sm[node*80 ..] ----
    if (role >= 2) {
        const int v0 = (role - 2) * 8;
        float* yb = sm + node * 80;
#pragma unroll
        for (int i = 0; i < 5; ++i)
#pragma unroll
            for (int p = 0; p < 4; ++p) {
                float lo, hi; unpack2(A[i * 4 + p], lo, hi);
                yb[(v0 + 2 * p) * 5 + i]     = lo;
                yb[(v0 + 2 * p + 1) * 5 + i] = hi;
            }
    }
    __syncthreads();

    // ---- phase B compute: out[4..8] ----
    for (int t = tid; t < 5 * NODES; t += TPB) {
        const int nd = t / 5, i = t - nd * 5;
        const float* yn = sm + nd * 80;
        const float* g2 = sm + 9216 + nd * 16;
        float o = 0.f;
#pragma unroll
        for (int v = 0; v < 16; ++v)
            o += (yn[v * 5 + i] * inv_in) * g2[v] * sm[OFF_W2S + 32 + v];
        const int gn = node0 + nd;
        if (gn < n) out[gn * 9 + 4 + i] = o * 0.25f;
    }
}

extern "C" void kernel_launch(void* const* d_in, const int* in_sizes, int n_in,
                              void* d_out, int out_size)
{
    const float* x    = (const float*)d_in[0];
    const float* w1_0 = (const float*)d_in[1];
    const float* w1_1 = (const float*)d_in[2];
    const float* w1_2 = (const float*)d_in[3];
    const float* w2_0 = (const float*)d_in[4];
    const float* w2_1 = (const float*)d_in[5];
    const float* w2_2 = (const float*)d_in[6];
    float* out = (float*)d_out;

    const int n = in_sizes[0] / 1152;
    const int smem = SM_FLOATS * (int)sizeof(float);   // 74944 B
    cudaFuncSetAttribute(readout_kernel, cudaFuncAttributeMaxDynamicSharedMemorySize, smem);
    const int blocks = (n + NODES - 1) / NODES;
    readout_kernel<<<blocks, TPB, smem>>>(x, w1_0, w1_1, w1_2, w2_0, w2_1, w2_2, out, n);
}

// round 10
// speedup vs baseline: 1.5949x; 1.5949x over previous
#include <cuda_runtime.h>

#define TPB     384
#define NODES   96
#define KU      8                   // u per chunk
#define NCHUNK  16
#define XS      76                  // per node per chunk: x0(8)+x1(24)+x2(40)+pad(4)
#define XBUF    (NODES * XS)        // 7296 floats per buffer
#define OFF_W0  (2 * XBUF)          // 14592 (w1_0: 6144 floats)
#define OFF_W1  (OFF_W0 + 6144)    // 20736 (w1_1: 2048)
#define OFF_W2  (OFF_W1 + 2048)    // 22784 (w1_2: 2048)
#define SM_FLOATS (OFF_W2 + 2048)  // 24832 floats = 99328 B -> 2 blocks/SM

typedef unsigned long long u64;

__device__ __forceinline__ u64 ffma2(u64 a, u64 b, u64 c) {
    u64 d;
    asm("fma.rn.f32x2 %0, %1, %2, %3;" : "=l"(d) : "l"(a), "l"(b), "l"(c));
    return d;
}
__device__ __forceinline__ u64 dup2(float v) {
    u64 d; unsigned u = __float_as_uint(v);
    asm("mov.b64 %0, {%1, %1};" : "=l"(d) : "r"(u));
    return d;
}
__device__ __forceinline__ void unpack2(u64 a, float& lo, float& hi) {
    lo = __uint_as_float((unsigned)a);
    hi = __uint_as_float((unsigned)(a >> 32));
}
__device__ __forceinline__ float silu(float v) {
    return v / (1.f + __expf(-v));
}

__global__ void __launch_bounds__(TPB, 2)
readout_kernel(const float* __restrict__ x,
               const float* __restrict__ w1_0, const float* __restrict__ w1_1,
               const float* __restrict__ w1_2, const float* __restrict__ w2_0,
               const float* __restrict__ w2_1, const float* __restrict__ w2_2,
               float* __restrict__ out, int n)
{
    extern __shared__ float sm[];
    const int tid = threadIdx.x;
    const int node0 = blockIdx.x * NODES;
    const unsigned smbase = (unsigned)__cvta_generic_to_shared(sm);

    // ---- cp.async staging: 96 nodes x 18 float4 per chunk = 1728 over 384 thr ----
    int pk_goff[5], pk_sc[5];
    unsigned pk_dst[5];
#pragma unroll
    for (int k = 0; k < 5; ++k) {
        int f = tid + k * TPB;
        if (f >= 18 * NODES) { pk_goff[k] = -1; pk_sc[k] = 0; pk_dst[k] = 0; continue; }
        int nd = f / 18, r = f - nd * 18;
        int sb, sc, dl;
        if (r < 2)      { sb = 4 * r;             sc = 8;  dl = 4 * r; }
        else if (r < 8) { sb = 128 + 4 * (r - 2); sc = 24; dl = 8 + 4 * (r - 2); }
        else            { sb = 512 + 4 * (r - 8); sc = 40; dl = 32 + 4 * (r - 8); }
        int gn = node0 + nd;
        if (gn >= n) gn = n - 1;                 // clamp; output stores are guarded
        pk_goff[k] = gn * 1152 + sb;
        pk_sc[k]   = sc;
        pk_dst[k]  = (unsigned)((nd * XS + dl) * 4);
    }
    auto stage = [&](int c, int buf) {
#pragma unroll
        for (int k = 0; k < 5; ++k) {
            if (pk_goff[k] < 0) break;
            const float* src = x + pk_goff[k] + pk_sc[k] * c;
            unsigned dst = smbase + (unsigned)(buf * (XBUF * 4)) + pk_dst[k];
            asm volatile("cp.async.cg.shared.global [%0], [%1], 16;"
                         :: "r"(dst), "l"(src));
        }
    };

    stage(0, 0);
    asm volatile("cp.async.commit_group;" ::: "memory");

    // weights to smem (covered by chunk-0 flight)
    for (int i = tid; i < 6144; i += TPB) sm[OFF_W0 + i] = w1_0[i];
    for (int i = tid; i < 2048; i += TPB) sm[OFF_W1 + i] = w1_1[i];
    for (int i = tid; i < 2048; i += TPB) sm[OFF_W2 + i] = w1_2[i];

    // 12 warps = 3 groups x 4 roles. SMSP0 gets the three role0 warps (750 iss),
    // each other SMSP gets {role1, role2, role3} (746) -> balanced.
    const int w    = tid >> 5;
    const int lane = tid & 31;
    const int s    = w & 3;
    const int g    = w >> 2;
    const int role = (s == 0) ? 0 : (1 + ((g + s) % 3));
    const int node = g * 32 + lane;

    u64 A[24];
#pragma unroll
    for (int i = 0; i < 24; ++i) A[i] = 0ull;

#pragma unroll 1
    for (int c = 0; c < NCHUNK; ++c) {
        asm volatile("cp.async.wait_group 0;" ::: "memory");
        __syncthreads();
        if (c + 1 < NCHUNK) {
            stage(c + 1, (c + 1) & 1);
            asm volatile("cp.async.commit_group;" ::: "memory");
        }
        const float* xr = sm + (c & 1) * XBUF + node * XS;
        const int u0 = KU * c;

        if (role == 0) {
            // y0: ALL 48 outputs as 24 f32x2 pairs
            float4 xa = *(const float4*)xr;
            float4 xb = *(const float4*)(xr + 4);
            float xe[8] = { xa.x, xa.y, xa.z, xa.w, xb.x, xb.y, xb.z, xb.w };
#pragma unroll
            for (int u = 0; u < 8; ++u) {
                u64 xs2 = dup2(xe[u]);
                const ulonglong2* wr =
                    (const ulonglong2*)(sm + OFF_W0 + (u0 + u) * 48);
#pragma unroll
                for (int m = 0; m < 12; m += 2) {
                    ulonglong2 pa = wr[m], pb = wr[m + 1];
                    A[2 * m + 0] = ffma2(xs2, pa.x, A[2 * m + 0]);
                    A[2 * m + 1] = ffma2(xs2, pa.y, A[2 * m + 1]);
                    A[2 * m + 2] = ffma2(xs2, pb.x, A[2 * m + 2]);
                    A[2 * m + 3] = ffma2(xs2, pb.y, A[2 * m + 3]);
                }
            }
        } else if (role == 1) {
            // y1: ALL 16 v x i=0..2 -> A[i*8+p], p = v-pair (2p,2p+1)
#pragma unroll
            for (int h = 0; h < 2; ++h) {
                const float4* xp = (const float4*)(xr + 8 + 12 * h);
                float4 q0 = xp[0], q1 = xp[1], q2 = xp[2];
                float xe[12] = { q0.x,q0.y,q0.z,q0.w, q1.x,q1.y,q1.z,q1.w,
                                 q2.x,q2.y,q2.z,q2.w };
#pragma unroll
                for (int ul = 0; ul < 4; ++ul) {
                    const ulonglong2* wr =
                        (const ulonglong2*)(sm + OFF_W1 + (u0 + 4 * h + ul) * 16);
                    {
                        ulonglong2 wa = wr[0], wb = wr[1];
#pragma unroll
                        for (int i = 0; i < 3; ++i) {
                            u64 xs2 = dup2(xe[3 * ul + i]);
                            A[i * 8 + 0] = ffma2(xs2, wa.x, A[i * 8 + 0]);
                            A[i * 8 + 1] = ffma2(xs2, wa.y, A[i * 8 + 1]);
                            A[i * 8 + 2] = ffma2(xs2, wb.x, A[i * 8 + 2]);
                            A[i * 8 + 3] = ffma2(xs2, wb.y, A[i * 8 + 3]);
                        }
                    }
                    {
                        ulonglong2 wc = wr[2], wd = wr[3];
#pragma unroll
                        for (int i = 0; i < 3; ++i) {
                            u64 xs2 = dup2(xe[3 * ul + i]);
                            A[i * 8 + 4] = ffma2(xs2, wc.x, A[i * 8 + 4]);
                            A[i * 8 + 5] = ffma2(xs2, wc.y, A[i * 8 + 5]);
                            A[i * 8 + 6] = ffma2(xs2, wd.x, A[i * 8 + 6]);
                            A[i * 8 + 7] = ffma2(xs2, wd.y, A[i * 8 + 7]);
                        }
                    }
                }
            }
        } else if (role == 2) {
            // y2, i=0,1: ALL 16 v -> A[i*8+p]
#pragma unroll
            for (int h = 0; h < 2; ++h) {
                const float4* xp = (const float4*)(xr + 32 + 20 * h);
                float4 q0 = xp[0], q1 = xp[1], q2 = xp[2], q3 = xp[3], q4 = xp[4];
                float xe[20] = { q0.x,q0.y,q0.z,q0.w, q1.x,q1.y,q1.z,q1.w,
                                 q2.x,q2.y,q2.z,q2.w, q3.x,q3.y,q3.z,q3.w,
                                 q4.x,q4.y,q4.z,q4.w };
#pragma unroll
                for (int ul = 0; ul < 4; ++ul) {
                    const ulonglong2* wr =
                        (const ulonglong2*)(sm + OFF_W2 + (u0 + 4 * h + ul) * 16);
                    ulonglong2 wa = wr[0], wb = wr[1], wc = wr[2], wd = wr[3];
#pragma unroll
                    for (int i = 0; i < 2; ++i) {
                        u64 xs2 = dup2(xe[5 * ul + i]);
                        A[i * 8 + 0] = ffma2(xs2, wa.x, A[i * 8 + 0]);
                        A[i * 8 + 1] = ffma2(xs2, wa.y, A[i * 8 + 1]);
                        A[i * 8 + 2] = ffma2(xs2, wb.x, A[i * 8 + 2]);
                        A[i * 8 + 3] = ffma2(xs2, wb.y, A[i * 8 + 3]);
                        A[i * 8 + 4] = ffma2(xs2, wc.x, A[i * 8 + 4]);
                        A[i * 8 + 5] = ffma2(xs2, wc.y, A[i * 8 + 5]);
                        A[i * 8 + 6] = ffma2(xs2, wd.x, A[i * 8 + 6]);
                        A[i * 8 + 7] = ffma2(xs2, wd.y, A[i * 8 + 7]);
                    }
                }
            }
        } else {
            // y2, i=2,3,4: ALL 16 v -> A[(i-2)*8+p]; w loads split 2+2 for regs
#pragma unroll
            for (int h = 0; h < 2; ++h) {
                const float4* xp = (const float4*)(xr + 32 + 20 * h);
                float4 q0 = xp[0], q1 = xp[1], q2 = xp[2], q3 = xp[3], q4 = xp[4];
                float xe[20] = { q0.x,q0.y,q0.z,q0.w, q1.x,q1.y,q1.z,q1.w,
                                 q2.x,q2.y,q2.z,q2.w, q3.x,q3.y,q3.z,q3.w,
                                 q4.x,q4.y,q4.z,q4.w };
#pragma unroll
                for (int ul = 0; ul < 4; ++ul) {
                    const ulonglong2* wr =
                        (const ulonglong2*)(sm + OFF_W2 + (u0 + 4 * h + ul) * 16);
                    {
                        ulonglong2 wa = wr[0], wb = wr[1];
#pragma unroll
                        for (int i = 0; i < 3; ++i) {
                            u64 xs2 = dup2(xe[5 * ul + 2 + i]);
                            A[i * 8 + 0] = ffma2(xs2, wa.x, A[i * 8 + 0]);
                            A[i * 8 + 1] = ffma2(xs2, wa.y, A[i * 8 + 1]);
                            A[i * 8 + 2] = ffma2(xs2, wb.x, A[i * 8 + 2]);
                            A[i * 8 + 3] = ffma2(xs2, wb.y, A[i * 8 + 3]);
                        }
                    }
                    {
                        ulonglong2 wc = wr[2], wd = wr[3];
#pragma unroll
                        for (int i = 0; i < 3; ++i) {
                            u64 xs2 = dup2(xe[5 * ul + 2 + i]);
                            A[i * 8 + 4] = ffma2(xs2, wc.x, A[i * 8 + 4]);
                            A[i * 8 + 5] = ffma2(xs2, wc.y, A[i * 8 + 5]);
                            A[i * 8 + 6] = ffma2(xs2, wd.x, A[i * 8 + 6]);
                            A[i * 8 + 7] = ffma2(xs2, wd.y, A[i * 8 + 7]);
                        }
                    }
                }
            }
        }
    }

    // ---- epilogue ----
    const float inv_in = 0.08838834764831845f;   // 1/sqrt(128)
    const int gn = node0 + node;

    // role0: o0 + gates. g lives in dead x-buffer 0 region, stride 33 (bank-spread).
    if (role == 0) {
        float y0v[48];
#pragma unroll
        for (int j = 0; j < 24; ++j) unpack2(A[j], y0v[2 * j], y0v[2 * j + 1]);
        float o = 0.f;
#pragma unroll
        for (int h = 0; h < 16; ++h)
            o += silu(y0v[h] * inv_in) * __ldg(w2_0 + h);
#pragma unroll
        for (int v = 0; v < 16; ++v)
            sm[node * 33 + v] = silu(y0v[16 + v] * inv_in);
#pragma unroll
        for (int v = 0; v < 16; ++v)
            sm[node * 33 + 16 + v] = silu(y0v[32 + v] * inv_in);
        if (gn < n) out[gn * 9 + 0] = o * 0.25f;
    }
    __syncthreads();

    if (role == 1) {
        float o0 = 0.f, o1 = 0.f, o2 = 0.f;
#pragma unroll
        for (int p = 0; p < 8; ++p) {
            float wa = __ldg(w2_1 + 2 * p)     * sm[node * 33 + 2 * p];
            float wb = __ldg(w2_1 + 2 * p + 1) * sm[node * 33 + 2 * p + 1];
            float lo, hi;
            unpack2(A[0 * 8 + p], lo, hi); o0 += lo * wa + hi * wb;
            unpack2(A[1 * 8 + p], lo, hi); o1 += lo * wa + hi * wb;
            unpack2(A[2 * 8 + p], lo, hi); o2 += lo * wa + hi * wb;
        }
        if (gn < n) {
            const float sc = inv_in * 0.25f;
            out[gn * 9 + 1] = o0 * sc;
            out[gn * 9 + 2] = o1 * sc;
            out[gn * 9 + 3] = o2 * sc;
        }
    } else if (role == 2) {
        float o0 = 0.f, o1 = 0.f;
#pragma unroll
        for (int p = 0; p < 8; ++p) {
            float wa = __ldg(w2_2 + 2 * p)     * sm[node * 33 + 16 + 2 * p];
            float wb = __ldg(w2_2 + 2 * p + 1) * sm[node * 33 + 16 + 2 * p + 1];
            float lo, hi;
            unpack2(A[0 * 8 + p], lo, hi); o0 += lo * wa + hi * wb;
            unpack2(A[1 * 8 + p], lo, hi); o1 += lo * wa + hi * wb;
        }
        if (gn < n) {
            const float sc = inv_in * 0.25f;
            out[gn * 9 + 4] = o0 * sc;
            out[gn * 9 + 5] = o1 * sc;
        }
    } else if (role == 3) {
        float o0 = 0.f, o1 = 0.f, o2 = 0.f;
#pragma unroll
        for (int p = 0; p < 8; ++p) {
            float wa = __ldg(w2_2 + 2 * p)     * sm[node * 33 + 16 + 2 * p];
            float wb = __ldg(w2_2 + 2 * p + 1) * sm[node * 33 + 16 + 2 * p + 1];
            float lo, hi;
            unpack2(A[0 * 8 + p], lo, hi); o0 += lo * wa + hi * wb;
            unpack2(A[1 * 8 + p], lo, hi); o1 += lo * wa + hi * wb;
            unpack2(A[2 * 8 + p], lo, hi); o2 += lo * wa + hi * wb;
        }
        if (gn < n) {
            const float sc = inv_in * 0.25f;
            out[gn * 9 + 6] = o0 * sc;
            out[gn * 9 + 7] = o1 * sc;
            out[gn * 9 + 8] = o2 * sc;
        }
    }
}

extern "C" void kernel_launch(void* const* d_in, const int* in_sizes, int n_in,
                              void* d_out, int out_size)
{
    const float* x    = (const float*)d_in[0];
    const float* w1_0 = (const float*)d_in[1];
    const float* w1_1 = (const float*)d_in[2];
    const float* w1_2 = (const float*)d_in[3];
    const float* w2_0 = (const float*)d_in[4];
    const float* w2_1 = (const float*)d_in[5];
    const float* w2_2 = (const float*)d_in[6];
    float* out = (float*)d_out;

    const int n = in_sizes[0] / 1152;
    const int smem = SM_FLOATS * (int)sizeof(float);   // 99328 B
    cudaFuncSetAttribute(readout_kernel, cudaFuncAttributeMaxDynamicSharedMemorySize, smem);
    const int blocks = (n + NODES - 1) / NODES;
    readout_kernel<<<blocks, TPB, smem>>>(x, w1_0, w1_1, w1_2, w2_0, w2_1, w2_2, out, n);
}